// round 9
// baseline (speedup 1.0000x reference)
#include <cuda_runtime.h>

// GAE backward scan — warp handles TWO sequences with interleaved independent
// carry chains (2x ILP over the shuffle-serial scan, 8 LDG.128 in flight).
//
// gae_t = d_t + m_t*gae_{t+1},  m_t = GL*(1-term_t), term ∈ {0,1} exactly.
// m binary -> propagation is a termination bitmask (ballot). With
// w_l = d_l*GL^l the within-chunk scan is a plain suffix sum; segment edges
// resolved by one variable-index shuffle:
//   gae_l = (S_l - S_{e_l+1}) * GL^{-l}  (+ carry*GL^32 if suffix unbroken).

#define GAMMA  0.99f
#define LMBDA  0.95f
#define GLF    (GAMMA * LMBDA)

#define B_TOT  8192
#define T_TOT  256
#define NTHREADS 128
#define WARPS_PER_BLOCK (NTHREADS / 32)
#define SEQ_PER_WARP 2
#define FULL 0xffffffffu

struct Chunk { float4 r, tm, v, nv; };

__device__ __forceinline__ Chunk load_chunk(const float4* __restrict__ reward,
                                            const float4* __restrict__ terminated,
                                            const float4* __restrict__ value,
                                            const float4* __restrict__ next_value,
                                            int g)
{
    Chunk c;
    c.r  = __ldcs(reward     + g);
    c.tm = __ldcs(terminated + g);
    c.v  = __ldcs(value      + g);
    c.nv = __ldcs(next_value + g);
    return c;
}

// one agent's segmented suffix scan for a 32-step chunk
__device__ __forceinline__ float comp_gae(float w, unsigned M, float carry,
                                          int lane, float invglp, float gl32)
{
    float S = w;
    #pragma unroll
    for (int off = 1; off < 32; off <<= 1) {
        const float t = __shfl_down_sync(FULL, S, off);
        if (lane + off < 32) S += t;
    }
    const unsigned Mge = M >> lane;
    const int src = Mge ? (lane + __ffs(Mge)) : 32;   // e_l + 1
    const float Sg = __shfl_sync(FULL, S, src);
    float acc = S - (src < 32 ? Sg : 0.0f);
    if (!Mge) acc = fmaf(carry, gl32, acc);
    return acc * invglp;
}

// full per-chunk processing for one sequence: ballot, scan, stores, carry.
__device__ __forceinline__ void process_chunk(const Chunk& cc, float4& carry,
                                              int g, int lane,
                                              float glp, float invglp, float gl32,
                                              float4* __restrict__ adv_out,
                                              float4* __restrict__ ret_out)
{
    const unsigned Mx = __ballot_sync(FULL, cc.tm.x != 0.0f);
    const unsigned My = __ballot_sync(FULL, cc.tm.y != 0.0f);
    const unsigned Mz = __ballot_sync(FULL, cc.tm.z != 0.0f);
    const unsigned Mw = __ballot_sync(FULL, cc.tm.w != 0.0f);

    const float ndx = 1.0f - cc.tm.x, ndy = 1.0f - cc.tm.y;
    const float ndz = 1.0f - cc.tm.z, ndw = 1.0f - cc.tm.w;
    const float wx = (cc.r.x + GAMMA * cc.nv.x * ndx - cc.v.x) * glp;
    const float wy = (cc.r.y + GAMMA * cc.nv.y * ndy - cc.v.y) * glp;
    const float wz = (cc.r.z + GAMMA * cc.nv.z * ndz - cc.v.z) * glp;
    const float ww = (cc.r.w + GAMMA * cc.nv.w * ndw - cc.v.w) * glp;

    float4 gae;
    gae.x = comp_gae(wx, Mx, carry.x, lane, invglp, gl32);
    gae.y = comp_gae(wy, My, carry.y, lane, invglp, gl32);
    gae.z = comp_gae(wz, Mz, carry.z, lane, invglp, gl32);
    gae.w = comp_gae(ww, Mw, carry.w, lane, invglp, gl32);

    adv_out[g] = gae;
    float4 ret;
    ret.x = gae.x + cc.v.x; ret.y = gae.y + cc.v.y;
    ret.z = gae.z + cc.v.z; ret.w = gae.w + cc.v.w;
    ret_out[g] = ret;

    carry.x = __shfl_sync(FULL, gae.x, 0);
    carry.y = __shfl_sync(FULL, gae.y, 0);
    carry.z = __shfl_sync(FULL, gae.z, 0);
    carry.w = __shfl_sync(FULL, gae.w, 0);
}

__global__ __launch_bounds__(NTHREADS, 6)
void gae_kernel(const float4* __restrict__ reward,
                const float4* __restrict__ terminated,
                const float4* __restrict__ value,
                const float4* __restrict__ next_value,
                float4* __restrict__ adv_out,
                float4* __restrict__ ret_out)
{
    const int warp  = blockIdx.x * WARPS_PER_BLOCK + (threadIdx.x >> 5);
    const int lane  = threadIdx.x & 31;
    const int baseA = (warp * SEQ_PER_WARP) * T_TOT + lane;   // sequence 2w
    const int baseB = baseA + T_TOT;                          // sequence 2w+1

    const float glp    = __powf(GLF, (float)lane);
    const float invglp = 1.0f / glp;
    const float gl32   = __powf(GLF, 32.0f);

    float4 carA = make_float4(0.f, 0.f, 0.f, 0.f);
    float4 carB = make_float4(0.f, 0.f, 0.f, 0.f);

    // prefetch both sequences' chunk 7
    Chunk bufA = load_chunk(reward, terminated, value, next_value, baseA + 7 * 32);
    Chunk bufB = load_chunk(reward, terminated, value, next_value, baseB + 7 * 32);

    #pragma unroll
    for (int c = T_TOT / 32 - 1; c >= 0; --c) {
        const Chunk ccA = bufA;
        const Chunk ccB = bufB;

        // issue both next-chunk load batches before either scan
        if (c > 0) {
            bufA = load_chunk(reward, terminated, value, next_value, baseA + (c - 1) * 32);
            bufB = load_chunk(reward, terminated, value, next_value, baseB + (c - 1) * 32);
        }

        // two independent scan chains — overlap on the SMSP
        process_chunk(ccA, carA, baseA + c * 32, lane, glp, invglp, gl32, adv_out, ret_out);
        process_chunk(ccB, carB, baseB + c * 32, lane, glp, invglp, gl32, adv_out, ret_out);
    }
}

extern "C" void kernel_launch(void* const* d_in, const int* in_sizes, int n_in,
                              void* d_out, int out_size)
{
    const float4* reward     = (const float4*)d_in[0];
    const float4* terminated = (const float4*)d_in[1];
    const float4* value      = (const float4*)d_in[2];
    const float4* next_value = (const float4*)d_in[3];

    const int n_elems = B_TOT * T_TOT * 4;            // floats per tensor
    float4* adv_out = (float4*)d_out;
    float4* ret_out = (float4*)((float*)d_out + n_elems);

    dim3 grid(B_TOT / (WARPS_PER_BLOCK * SEQ_PER_WARP));   // 1024 blocks
    dim3 block(NTHREADS);
    gae_kernel<<<grid, block>>>(reward, terminated, value, next_value,
                                adv_out, ret_out);
}